// round 7
// baseline (speedup 1.0000x reference)
#include <cuda_runtime.h>
#include <math.h>

#define NB 4096
#define NK 1024
#define ND 128
#define NQ 4096
#define EPSV 1e-6f
#define SCALE 4294967296.0   // 2^32 fixed-point for deterministic accumulation

typedef unsigned long long u64;
typedef unsigned int u32;

// Scratch (device globals — no allocation allowed in kernel_launch)
__device__ u64   g_skey[ND * NK];     // sorted packed keys, layout [d][i]
__device__ u32   g_lutpair[ND * NQ];  // per-bucket start|end<<16 (fallback only)
__device__ uint4 g_rec[ND * NQ];      // 16B: kl_enc,k0_enc,k1_enc, idx+cnt pack
__device__ float g_vmin[ND], g_vmax[ND];
__device__ int   g_imin[ND], g_imax[ND];
__device__ u64   g_accum;             // fixed-point loss sum (deterministic)
__device__ u32   g_done;              // finished-block counter

// float -> order-preserving u32 (ascending)
__device__ __forceinline__ u32 enc_f32(float v) {
    u32 b = __float_as_uint(v);
    return (b & 0x80000000u) ? ~b : (b | 0x80000000u);
}
__device__ __forceinline__ float dec_f32(u32 u) {
    u32 b = (u & 0x80000000u) ? (u ^ 0x80000000u) : ~u;
    return __uint_as_float(b);
}

// Exactly monotone bucket map: fp add, mul by +const, float->int trunc are all
// monotone nondecreasing, so v1 <= v2 => bucket(v1) <= bucket(v2), and
// b1 < b2 => v1 < v2 (strict). Equal values map to equal buckets.
__device__ __forceinline__ int bucket_of(float v) {
    float f = (v + 6.0f) * ((float)NQ / 12.0f);
    f = fminf(fmaxf(f, 0.0f), (float)(NQ - 1));
    return (int)f;
}

// ---------------------------------------------------------------------------
// Kernel 1: per-column COUNTING sort of packed (value,index) u64 keys.
// grid = ND blocks, 512 threads x 2 elements. Emits sorted keys + lutpair.
// ---------------------------------------------------------------------------
__global__ void __launch_bounds__(512) sort_columns_kernel(const float* __restrict__ cent) {
    __shared__ __align__(16) int s_hist[NQ];       // 16 KB
    __shared__ __align__(16) int s_pref[NQ + 4];   // 16 KB (exclusive prefix)
    __shared__ u64 s_tmp[NK];                      // 8 KB (arrival-order scatter)
    __shared__ u64 s_keys[NK];                     // 8 KB (final sorted)
    __shared__ int s_wsum[16];

    const int d = blockIdx.x;
    const int i = threadIdx.x;
    const int lane = i & 31, w = i >> 5;

    if (d == 0 && i == 0) { g_accum = 0ULL; g_done = 0u; }  // per-launch reset

    const float v0 = cent[i * ND + d];
    const float v1 = cent[(i + 512) * ND + d];
    const u64 k0e = ((u64)enc_f32(v0) << 32) | (u32)i;
    const u64 k1e = ((u64)enc_f32(v1) << 32) | (u32)(i + 512);
    const int b0 = bucket_of(v0), b1 = bucket_of(v1);

    ((int4*)s_hist)[i] = make_int4(0, 0, 0, 0);
    ((int4*)s_hist)[i + 512] = make_int4(0, 0, 0, 0);
    __syncthreads();
    const int r0 = atomicAdd(&s_hist[b0], 1);
    const int r1 = atomicAdd(&s_hist[b1], 1);
    __syncthreads();

    // prefix sum over 4096 bins (8 per thread)
    const int4 ca = ((const int4*)s_hist)[2 * i];
    const int4 cb = ((const int4*)s_hist)[2 * i + 1];
    const int s = ca.x + ca.y + ca.z + ca.w + cb.x + cb.y + cb.z + cb.w;
    int incl = s;
#pragma unroll
    for (int off = 1; off < 32; off <<= 1) {
        int t = __shfl_up_sync(0xffffffffu, incl, off);
        if (lane >= off) incl += t;
    }
    if (lane == 31) s_wsum[w] = incl;
    __syncthreads();
    if (w == 0) {
        int ws = (lane < 16) ? s_wsum[lane] : 0;
#pragma unroll
        for (int off = 1; off < 16; off <<= 1) {
            int t = __shfl_up_sync(0xffffffffu, ws, off);
            if (lane >= off) ws += t;
        }
        if (lane < 16) s_wsum[lane] = ws;
    }
    __syncthreads();
    {
        int p0 = (w > 0 ? s_wsum[w - 1] : 0) + (incl - s);
        int p1 = p0 + ca.x, p2 = p1 + ca.y, p3 = p2 + ca.z, p4 = p3 + ca.w;
        int p5 = p4 + cb.x, p6 = p5 + cb.y, p7 = p6 + cb.z;
        ((int4*)s_pref)[2 * i]     = make_int4(p0, p1, p2, p3);
        ((int4*)s_pref)[2 * i + 1] = make_int4(p4, p5, p6, p7);
    }
    if (i == 0) s_pref[NQ] = NK;
    __syncthreads();

    // scatter in arrival order
    const int st0 = s_pref[b0], st1 = s_pref[b1];
    s_tmp[st0 + r0] = k0e;
    s_tmp[st1 + r1] = k1e;
    __syncthreads();

    // parallel rank placement on unique full keys (deterministic)
    {
        const int cnt0 = s_hist[b0];
        int rank = 0;
        for (int j = 0; j < cnt0; j++) rank += (s_tmp[st0 + j] < k0e);
        s_keys[st0 + rank] = k0e;
        const int cnt1 = s_hist[b1];
        rank = 0;
        for (int j = 0; j < cnt1; j++) rank += (s_tmp[st1 + j] < k1e);
        s_keys[st1 + rank] = k1e;
    }
    __syncthreads();

    // sorted keys + lutpair (coalesced)
    g_skey[d * NK + i]       = s_keys[i];
    g_skey[d * NK + i + 512] = s_keys[i + 512];
#pragma unroll
    for (int t = 0; t < 8; t++) {
        const int q = i + t * 512;
        g_lutpair[d * NQ + q] = (u32)s_pref[q] | ((u32)s_pref[q + 1] << 16);
    }

    if (i == 0) {
        // min: first sorted key already has smallest index among min-ties
        g_vmin[d] = dec_f32((u32)(s_keys[0] >> 32));
        g_imin[d] = (int)(s_keys[0] & 1023u);
        // max: first occurrence (smallest idx) = start of the max-value run
        u32 umax = (u32)(s_keys[NK - 1] >> 32);
        int j = NK - 1;
        while (j > 0 && (u32)(s_keys[j - 1] >> 32) == umax) j--;
        g_vmax[d] = dec_f32(umax);
        g_imax[d] = (int)(s_keys[j] & 1023u);
    }
}

// ---------------------------------------------------------------------------
// Kernel 1b: emit 16B bucket records with full-chip parallelism.
// grid = ND*8 blocks, 512 threads, one record per thread.
// ---------------------------------------------------------------------------
__global__ void __launch_bounds__(512) record_kernel() {
    const int d = blockIdx.x >> 3;
    const int q = ((blockIdx.x & 7) << 9) | threadIdx.x;
    const u32 pr = g_lutpair[d * NQ + q];
    const int st = (int)(pr & 0xffffu), en = (int)(pr >> 16);
    const int base = d * NK;
    const u64 kl = g_skey[base + max(st - 1, 0)];
    const u64 k0 = g_skey[base + min(st, NK - 1)];
    const u64 k1 = g_skey[base + min(st + 1, NK - 1)];
    const u32 cc = (u32)min(en - st, 3);
    g_rec[d * NQ + q] = make_uint4(
        (u32)(kl >> 32), (u32)(k0 >> 32), (u32)(k1 >> 32),
        ((u32)kl & 1023u) | (((u32)k0 & 1023u) << 10) |
        (((u32)k1 & 1023u) << 20) | (cc << 30));
}

// ---------------------------------------------------------------------------
// Nearest-centroid resolve: one 16B record load resolves ~90% of queries
// (cnt<=1 or target<=k1); rare fallback loads lutpair + scans sorted keys.
// ---------------------------------------------------------------------------
__device__ __forceinline__ int resolve_near(const float xv, const int d) {
    const u32 te = enc_f32(xv);
    const int q = bucket_of(xv);
    const uint4 r = __ldg(&g_rec[d * NQ + q]);
    const u32 cc = r.w >> 30;

    u32 el, er, il, ir;
    if (cc == 0u || te <= r.y) {              // lower_bound = start
        el = r.x; il = r.w & 1023u;
        er = r.y; ir = (r.w >> 10) & 1023u;
    } else if (cc == 1u || te <= r.z) {       // lower_bound = start+1
        el = r.y; il = (r.w >> 10) & 1023u;
        er = r.z; ir = (r.w >> 20) & 1023u;
    } else {                                  // cnt>=2 and target beyond k1
        const u32 pr = __ldg(&g_lutpair[d * NQ + q]);
        const int st = (int)(pr & 0xffffu), en = (int)(pr >> 16);
        const int base = d * NK;
        const u64 target = ((u64)te) << 32;
        u64 prev = ((u64)r.z << 32) | ((r.w >> 20) & 1023u);
        u64 right = prev;
        bool found = false;
        for (int j = st + 2; j < en; j++) {
            u64 cur = __ldg(&g_skey[base + j]);
            if (cur >= target) { right = cur; found = true; break; }
            prev = cur;
        }
        if (!found) right = (en < NK) ? __ldg(&g_skey[base + en]) : prev;
        el = (u32)(prev >> 32);  il = (u32)prev & 1023u;
        er = (u32)(right >> 32); ir = (u32)right & 1023u;
    }

    const float vl = dec_f32(el), vr = dec_f32(er);
    float sl = xv - vl; sl *= sl;     // compare squares, like reference
    float sr = xv - vr; sr *= sr;
    return (sl < sr) ? (int)il : (sr < sl) ? (int)ir : min((int)il, (int)ir);
}

// ---------------------------------------------------------------------------
// Kernel 2: one block per FOUR rows, ND threads (thread = dim d, all rows).
// Four independent resolve chains (MLP=4), packed dual histograms per row,
// atomicAdd-return running-max mode, butterfly shfl reductions,
// deterministic fixed-point global accumulation; last block writes the mean.
// ---------------------------------------------------------------------------
__global__ void __launch_bounds__(ND) row_kernel(const float* __restrict__ x,
                                                 const float* __restrict__ cent,
                                                 float* __restrict__ out) {
    __shared__ u32 hist[4][NK];       // 16 KB, packed (near | far<<16)
    __shared__ u32 s_key[8][4];
    __shared__ float s_sum[12][4];

    const int b0 = blockIdx.x * 4;
    const int d = threadIdx.x;
    const int warp = d >> 5, lane = d & 31;

    {
        uint4 z = make_uint4(0, 0, 0, 0);
#pragma unroll
        for (int r = 0; r < 4; r++) {
            ((uint4*)hist[r])[d] = z;
            ((uint4*)hist[r])[d + 128] = z;
        }
    }

    float xv[4];
#pragma unroll
    for (int r = 0; r < 4; r++) xv[r] = x[(b0 + r) * ND + d];

    int n_idx[4];
#pragma unroll
    for (int r = 0; r < 4; r++) n_idx[r] = resolve_near(xv[r], d);

    // ---- farthest: one of the column extremes ----
    const float vmin = g_vmin[d], vmax = g_vmax[d];
    const int   imin = g_imin[d], imax = g_imax[d];
    int f_idx[4];
#pragma unroll
    for (int r = 0; r < 4; r++) {
        float sm = xv[r] - vmin; sm *= sm;
        float sM = xv[r] - vmax; sM *= sM;
        f_idx[r] = (sm > sM) ? imin : (sM > sm) ? imax : min(imin, imax);
    }

    __syncthreads();  // hist zeroing complete
    u32 key[8];
#pragma unroll
    for (int r = 0; r < 4; r++) {
        u32 cn = (atomicAdd(&hist[r][n_idx[r]], 1u) & 0xffffu) + 1u;
        u32 cf = (atomicAdd(&hist[r][f_idx[r]], 0x10000u) >> 16) + 1u;
        key[2 * r]     = (cn << 10) | (1023u - (u32)n_idx[r]);
        key[2 * r + 1] = (cf << 10) | (1023u - (u32)f_idx[r]);
    }

    // Running-max mode: last incrementer of each bin sees its final count,
    // so max over thread keys = (max count, smallest bin on ties).
#pragma unroll
    for (int s = 16; s > 0; s >>= 1) {
#pragma unroll
        for (int t = 0; t < 8; t++)
            key[t] = max(key[t], __shfl_xor_sync(0xffffffffu, key[t], s));
    }
    if (lane == 0) {
#pragma unroll
        for (int t = 0; t < 8; t++) s_key[t][warp] = key[t];
    }
    __syncthreads();
    int mp[4], mn[4];
#pragma unroll
    for (int r = 0; r < 4; r++) {
        u32 kp = max(max(s_key[2*r][0], s_key[2*r][1]), max(s_key[2*r][2], s_key[2*r][3]));
        u32 kn = max(max(s_key[2*r+1][0], s_key[2*r+1][1]), max(s_key[2*r+1][2], s_key[2*r+1][3]));
        mp[r] = 1023 - (int)(kp & 1023u);
        mn[r] = 1023 - (int)(kn & 1023u);
    }

    // ---- triplet margin loss (swap=True), eps added per element ----
    float u[12];
#pragma unroll
    for (int r = 0; r < 4; r++) {
        float pv = __ldg(&cent[mp[r] * ND + d]);
        float nv = __ldg(&cent[mn[r] * ND + d]);
        float a = xv[r] - pv + EPSV;
        float b = xv[r] - nv + EPSV;
        float c = pv - nv + EPSV;
        u[3 * r]     = a * a;
        u[3 * r + 1] = b * b;
        u[3 * r + 2] = c * c;
    }
#pragma unroll
    for (int s = 16; s > 0; s >>= 1) {
#pragma unroll
        for (int t = 0; t < 12; t++)
            u[t] += __shfl_xor_sync(0xffffffffu, u[t], s);
    }
    if (lane == 0) {
#pragma unroll
        for (int t = 0; t < 12; t++) s_sum[t][warp] = u[t];
    }
    __syncthreads();
    if (d == 0) {
        u64 fx = 0ULL;
#pragma unroll
        for (int r = 0; r < 4; r++) {
            float r0 = s_sum[3*r][0] + s_sum[3*r][1] + s_sum[3*r][2] + s_sum[3*r][3];
            float r1 = s_sum[3*r+1][0] + s_sum[3*r+1][1] + s_sum[3*r+1][2] + s_sum[3*r+1][3];
            float r2 = s_sum[3*r+2][0] + s_sum[3*r+2][1] + s_sum[3*r+2][2] + s_sum[3*r+2][3];
            float dp = sqrtf(r0);
            float dn = fminf(sqrtf(r1), sqrtf(r2));
            float loss = fmaxf(dp - dn + 1.0f, 0.0f);
            fx += (u64)__double2ll_rn((double)loss * SCALE);
        }
        // deterministic fixed-point accumulation (integer adds are associative)
        atomicAdd(&g_accum, fx);
        __threadfence();
        if (atomicAdd(&g_done, 1u) == gridDim.x - 1) {
            u64 acc = atomicAdd(&g_accum, 0ULL);
            out[0] = (float)((double)acc * (1.0 / (4096.0 * SCALE)));
        }
    }
}

extern "C" void kernel_launch(void* const* d_in, const int* in_sizes, int n_in,
                              void* d_out, int out_size) {
    const float* input_features = (const float*)d_in[0];  // [4096, 128]
    const float* centroids      = (const float*)d_in[1];  // [1024, 128]
    float* out = (float*)d_out;

    sort_columns_kernel<<<ND, 512>>>(centroids);
    record_kernel<<<ND * 8, 512>>>();
    row_kernel<<<NB / 4, ND>>>(input_features, centroids, out);
}

// round 8
// speedup vs baseline: 1.1000x; 1.1000x over previous
#include <cuda_runtime.h>
#include <math.h>

#define NB 4096
#define NK 1024
#define ND 128
#define NQ 2048
#define EPSV 1e-6f
#define SCALE 4294967296.0   // 2^32 fixed-point for deterministic accumulation

typedef unsigned long long u64;
typedef unsigned int u32;

// Scratch (device globals — no allocation allowed in kernel_launch)
__device__ u64   g_skey[ND * NK];     // sorted packed keys, layout [d][i]
__device__ u32   g_lutpair[ND * NQ];  // per-bucket start|end<<16 (fallback only)
__device__ uint4 g_rec[ND * NQ];      // 16B: kl_enc,k0_enc,k1_enc, idx+cnt pack
__device__ float g_vmin[ND], g_vmax[ND];
__device__ int   g_imin[ND], g_imax[ND];
__device__ u64   g_accum;             // fixed-point loss sum (deterministic)
__device__ u32   g_done;              // finished-block counter

// float -> order-preserving u32 (ascending)
__device__ __forceinline__ u32 enc_f32(float v) {
    u32 b = __float_as_uint(v);
    return (b & 0x80000000u) ? ~b : (b | 0x80000000u);
}
__device__ __forceinline__ float dec_f32(u32 u) {
    u32 b = (u & 0x80000000u) ? (u ^ 0x80000000u) : ~u;
    return __uint_as_float(b);
}

// Exactly monotone bucket map: fp add, mul by +const, float->int trunc are all
// monotone nondecreasing, so v1 <= v2 => bucket(v1) <= bucket(v2), and
// b1 < b2 => v1 < v2 (strict). Equal values map to equal buckets.
__device__ __forceinline__ int bucket_of(float v) {
    float f = (v + 6.0f) * ((float)NQ / 12.0f);
    f = fminf(fmaxf(f, 0.0f), (float)(NQ - 1));
    return (int)f;
}

// ---------------------------------------------------------------------------
// Kernel 1: per-column COUNTING sort of packed (value,index) u64 keys.
// grid = ND blocks, 512 threads x 2 elements (r5 shape, NQ=2048).
// ---------------------------------------------------------------------------
__global__ void __launch_bounds__(512) sort_columns_kernel(const float* __restrict__ cent) {
    __shared__ __align__(16) int s_hist[NQ];       // 8 KB
    __shared__ __align__(16) int s_pref[NQ + 4];   // 8 KB (exclusive prefix)
    __shared__ u64 s_tmp[NK];                      // 8 KB (arrival-order scatter)
    __shared__ u64 s_keys[NK];                     // 8 KB (final sorted)
    __shared__ int s_wsum[16];

    const int d = blockIdx.x;
    const int i = threadIdx.x;
    const int lane = i & 31, w = i >> 5;

    if (d == 0 && i == 0) { g_accum = 0ULL; g_done = 0u; }  // per-launch reset

    const float v0 = cent[i * ND + d];
    const float v1 = cent[(i + 512) * ND + d];
    const u64 k0e = ((u64)enc_f32(v0) << 32) | (u32)i;
    const u64 k1e = ((u64)enc_f32(v1) << 32) | (u32)(i + 512);
    const int b0 = bucket_of(v0), b1 = bucket_of(v1);

    ((int4*)s_hist)[i] = make_int4(0, 0, 0, 0);   // NQ ints = 512 int4
    __syncthreads();
    const int r0 = atomicAdd(&s_hist[b0], 1);
    const int r1 = atomicAdd(&s_hist[b1], 1);
    __syncthreads();

    // prefix sum over 2048 bins (4 per thread)
    const int4 c = ((const int4*)s_hist)[i];
    const int s = c.x + c.y + c.z + c.w;
    int incl = s;
#pragma unroll
    for (int off = 1; off < 32; off <<= 1) {
        int t = __shfl_up_sync(0xffffffffu, incl, off);
        if (lane >= off) incl += t;
    }
    if (lane == 31) s_wsum[w] = incl;
    __syncthreads();
    if (w == 0) {
        int ws = (lane < 16) ? s_wsum[lane] : 0;
#pragma unroll
        for (int off = 1; off < 16; off <<= 1) {
            int t = __shfl_up_sync(0xffffffffu, ws, off);
            if (lane >= off) ws += t;
        }
        if (lane < 16) s_wsum[lane] = ws;
    }
    __syncthreads();
    {
        int p0 = (w > 0 ? s_wsum[w - 1] : 0) + (incl - s);
        ((int4*)s_pref)[i] = make_int4(p0, p0 + c.x, p0 + c.x + c.y, p0 + c.x + c.y + c.z);
    }
    if (i == 0) s_pref[NQ] = NK;
    __syncthreads();

    // scatter in arrival order
    const int st0 = s_pref[b0], st1 = s_pref[b1];
    s_tmp[st0 + r0] = k0e;
    s_tmp[st1 + r1] = k1e;
    __syncthreads();

    // parallel rank placement on unique full keys (deterministic)
    {
        const int cnt0 = s_hist[b0];
        int rank = 0;
        for (int j = 0; j < cnt0; j++) rank += (s_tmp[st0 + j] < k0e);
        s_keys[st0 + rank] = k0e;
        const int cnt1 = s_hist[b1];
        rank = 0;
        for (int j = 0; j < cnt1; j++) rank += (s_tmp[st1 + j] < k1e);
        s_keys[st1 + rank] = k1e;
    }
    __syncthreads();

    // sorted keys + lutpair (coalesced)
    g_skey[d * NK + i]       = s_keys[i];
    g_skey[d * NK + i + 512] = s_keys[i + 512];
#pragma unroll
    for (int t = 0; t < 4; t++) {
        const int q = i + t * 512;
        g_lutpair[d * NQ + q] = (u32)s_pref[q] | ((u32)s_pref[q + 1] << 16);
    }

    if (i == 0) {
        // min: first sorted key already has smallest index among min-ties
        g_vmin[d] = dec_f32((u32)(s_keys[0] >> 32));
        g_imin[d] = (int)(s_keys[0] & 1023u);
        // max: first occurrence (smallest idx) = start of the max-value run
        u32 umax = (u32)(s_keys[NK - 1] >> 32);
        int j = NK - 1;
        while (j > 0 && (u32)(s_keys[j - 1] >> 32) == umax) j--;
        g_vmax[d] = dec_f32(umax);
        g_imax[d] = (int)(s_keys[j] & 1023u);
    }
}

// ---------------------------------------------------------------------------
// Kernel 1b: emit 16B bucket records with full-chip parallelism.
// grid = ND*4 blocks, 512 threads, one record per thread.
// ---------------------------------------------------------------------------
__global__ void __launch_bounds__(512) record_kernel() {
    const int d = blockIdx.x >> 2;
    const int q = ((blockIdx.x & 3) << 9) | threadIdx.x;
    const u32 pr = g_lutpair[d * NQ + q];
    const int st = (int)(pr & 0xffffu), en = (int)(pr >> 16);
    const int base = d * NK;
    const u64 kl = g_skey[base + max(st - 1, 0)];
    const u64 k0 = g_skey[base + min(st, NK - 1)];
    const u64 k1 = g_skey[base + min(st + 1, NK - 1)];
    const u32 cc = (u32)min(en - st, 3);
    g_rec[d * NQ + q] = make_uint4(
        (u32)(kl >> 32), (u32)(k0 >> 32), (u32)(k1 >> 32),
        ((u32)kl & 1023u) | (((u32)k0 & 1023u) << 10) |
        (((u32)k1 & 1023u) << 20) | (cc << 30));
}

// ---------------------------------------------------------------------------
// Nearest-centroid resolve: one 16B record load resolves most queries
// (cnt<=1 or target<=k1); fallback loads lutpair + scans sorted keys.
// ---------------------------------------------------------------------------
__device__ __forceinline__ int resolve_near(const float xv, const int d) {
    const u32 te = enc_f32(xv);
    const int q = bucket_of(xv);
    const uint4 r = __ldg(&g_rec[d * NQ + q]);
    const u32 cc = r.w >> 30;

    u32 el, er, il, ir;
    if (cc == 0u || te <= r.y) {              // lower_bound = start
        el = r.x; il = r.w & 1023u;
        er = r.y; ir = (r.w >> 10) & 1023u;
    } else if (cc == 1u || te <= r.z) {       // lower_bound = start+1
        el = r.y; il = (r.w >> 10) & 1023u;
        er = r.z; ir = (r.w >> 20) & 1023u;
    } else {                                  // cnt>=2 and target beyond k1
        const u32 pr = __ldg(&g_lutpair[d * NQ + q]);
        const int st = (int)(pr & 0xffffu), en = (int)(pr >> 16);
        const int base = d * NK;
        const u64 target = ((u64)te) << 32;
        u64 prev = ((u64)r.z << 32) | ((r.w >> 20) & 1023u);
        u64 right = prev;
        bool found = false;
        for (int j = st + 2; j < en; j++) {
            u64 cur = __ldg(&g_skey[base + j]);
            if (cur >= target) { right = cur; found = true; break; }
            prev = cur;
        }
        if (!found) right = (en < NK) ? __ldg(&g_skey[base + en]) : prev;
        el = (u32)(prev >> 32);  il = (u32)prev & 1023u;
        er = (u32)(right >> 32); ir = (u32)right & 1023u;
    }

    const float vl = dec_f32(el), vr = dec_f32(er);
    float sl = xv - vl; sl *= sl;     // compare squares, like reference
    float sr = xv - vr; sr *= sr;
    return (sl < sr) ? (int)il : (sr < sl) ? (int)ir : min((int)il, (int)ir);
}

// ---------------------------------------------------------------------------
// Kernel 2: one block per FOUR rows, ND threads (thread = dim d, all rows).
// 8-bit packed histograms: count<=128 fits a byte, so 4 rows of "near" share
// one u32 array (byte lane r) and 4 rows of "far" share another -> 8 KB smem,
// half the zeroing. atomicAdd cannot carry across lanes (max 128 < 256).
// ---------------------------------------------------------------------------
__global__ void __launch_bounds__(ND) row_kernel(const float* __restrict__ x,
                                                 const float* __restrict__ cent,
                                                 float* __restrict__ out) {
    __shared__ u32 hist_n[NK], hist_f[NK];   // 8 KB total
    __shared__ u32 s_key[8][4];
    __shared__ float s_sum[12][4];

    const int b0 = blockIdx.x * 4;
    const int d = threadIdx.x;
    const int warp = d >> 5, lane = d & 31;

    {
        uint4 z = make_uint4(0, 0, 0, 0);
        ((uint4*)hist_n)[d] = z; ((uint4*)hist_n)[d + 128] = z;
        ((uint4*)hist_f)[d] = z; ((uint4*)hist_f)[d + 128] = z;
    }

    float xv[4];
#pragma unroll
    for (int r = 0; r < 4; r++) xv[r] = x[(b0 + r) * ND + d];

    int n_idx[4];
#pragma unroll
    for (int r = 0; r < 4; r++) n_idx[r] = resolve_near(xv[r], d);

    // ---- farthest: one of the column extremes ----
    const float vmin = g_vmin[d], vmax = g_vmax[d];
    const int   imin = g_imin[d], imax = g_imax[d];
    int f_idx[4];
#pragma unroll
    for (int r = 0; r < 4; r++) {
        float sm = xv[r] - vmin; sm *= sm;
        float sM = xv[r] - vmax; sM *= sM;
        f_idx[r] = (sm > sM) ? imin : (sM > sm) ? imax : min(imin, imax);
    }

    __syncthreads();  // hist zeroing complete
    u32 key[8];
#pragma unroll
    for (int r = 0; r < 4; r++) {
        u32 on = atomicAdd(&hist_n[n_idx[r]], 1u << (8 * r));
        u32 of = atomicAdd(&hist_f[f_idx[r]], 1u << (8 * r));
        u32 cn = ((on >> (8 * r)) & 0xffu) + 1u;
        u32 cf = ((of >> (8 * r)) & 0xffu) + 1u;
        key[2 * r]     = (cn << 10) | (1023u - (u32)n_idx[r]);
        key[2 * r + 1] = (cf << 10) | (1023u - (u32)f_idx[r]);
    }

    // Running-max mode: last incrementer of each bin sees its final count,
    // so max over thread keys = (max count, smallest bin on ties).
#pragma unroll
    for (int s = 16; s > 0; s >>= 1) {
#pragma unroll
        for (int t = 0; t < 8; t++)
            key[t] = max(key[t], __shfl_xor_sync(0xffffffffu, key[t], s));
    }
    if (lane == 0) {
#pragma unroll
        for (int t = 0; t < 8; t++) s_key[t][warp] = key[t];
    }
    __syncthreads();
    int mp[4], mn[4];
#pragma unroll
    for (int r = 0; r < 4; r++) {
        u32 kp = max(max(s_key[2*r][0], s_key[2*r][1]), max(s_key[2*r][2], s_key[2*r][3]));
        u32 kn = max(max(s_key[2*r+1][0], s_key[2*r+1][1]), max(s_key[2*r+1][2], s_key[2*r+1][3]));
        mp[r] = 1023 - (int)(kp & 1023u);
        mn[r] = 1023 - (int)(kn & 1023u);
    }

    // ---- triplet margin loss (swap=True), eps added per element ----
    float u[12];
#pragma unroll
    for (int r = 0; r < 4; r++) {
        float pv = __ldg(&cent[mp[r] * ND + d]);
        float nv = __ldg(&cent[mn[r] * ND + d]);
        float a = xv[r] - pv + EPSV;
        float b = xv[r] - nv + EPSV;
        float c = pv - nv + EPSV;
        u[3 * r]     = a * a;
        u[3 * r + 1] = b * b;
        u[3 * r + 2] = c * c;
    }
#pragma unroll
    for (int s = 16; s > 0; s >>= 1) {
#pragma unroll
        for (int t = 0; t < 12; t++)
            u[t] += __shfl_xor_sync(0xffffffffu, u[t], s);
    }
    if (lane == 0) {
#pragma unroll
        for (int t = 0; t < 12; t++) s_sum[t][warp] = u[t];
    }
    __syncthreads();
    if (d == 0) {
        u64 fx = 0ULL;
#pragma unroll
        for (int r = 0; r < 4; r++) {
            float r0 = s_sum[3*r][0] + s_sum[3*r][1] + s_sum[3*r][2] + s_sum[3*r][3];
            float r1 = s_sum[3*r+1][0] + s_sum[3*r+1][1] + s_sum[3*r+1][2] + s_sum[3*r+1][3];
            float r2 = s_sum[3*r+2][0] + s_sum[3*r+2][1] + s_sum[3*r+2][2] + s_sum[3*r+2][3];
            float dp = sqrtf(r0);
            float dn = fminf(sqrtf(r1), sqrtf(r2));
            float loss = fmaxf(dp - dn + 1.0f, 0.0f);
            fx += (u64)__double2ll_rn((double)loss * SCALE);
        }
        // deterministic fixed-point accumulation (integer adds are associative)
        atomicAdd(&g_accum, fx);
        __threadfence();
        if (atomicAdd(&g_done, 1u) == gridDim.x - 1) {
            u64 acc = atomicAdd(&g_accum, 0ULL);
            out[0] = (float)((double)acc * (1.0 / (4096.0 * SCALE)));
        }
    }
}

extern "C" void kernel_launch(void* const* d_in, const int* in_sizes, int n_in,
                              void* d_out, int out_size) {
    const float* input_features = (const float*)d_in[0];  // [4096, 128]
    const float* centroids      = (const float*)d_in[1];  // [1024, 128]
    float* out = (float*)d_out;

    sort_columns_kernel<<<ND, 512>>>(centroids);
    record_kernel<<<ND * 4, 512>>>();
    row_kernel<<<NB / 4, ND>>>(input_features, centroids, out);
}

// round 9
// speedup vs baseline: 1.3222x; 1.2020x over previous
#include <cuda_runtime.h>
#include <math.h>

#define NB 4096
#define NK 1024
#define ND 128
#define NQ 2048
#define EPSV 1e-6f
#define SCALE 4294967296.0   // 2^32 fixed-point for deterministic accumulation

typedef unsigned long long u64;
typedef unsigned int u32;

// Scratch (device globals — no allocation allowed in kernel_launch)
__device__ u64   g_skey[ND * NK];     // sorted packed keys, layout [d][i]
__device__ u32   g_lutpair[ND * NQ];  // per-bucket start|end<<16 (fallback only)
__device__ uint4 g_rec[ND * NQ];      // 16B: kl_enc,k0_enc,k1_enc, idx+cnt pack
__device__ float g_vmin[ND], g_vmax[ND];
__device__ int   g_imin[ND], g_imax[ND];
__device__ u64   g_accum;             // fixed-point loss sum (deterministic)
__device__ u32   g_done;              // finished-block counter

// float -> order-preserving u32 (ascending)
__device__ __forceinline__ u32 enc_f32(float v) {
    u32 b = __float_as_uint(v);
    return (b & 0x80000000u) ? ~b : (b | 0x80000000u);
}
__device__ __forceinline__ float dec_f32(u32 u) {
    u32 b = (u & 0x80000000u) ? (u ^ 0x80000000u) : ~u;
    return __uint_as_float(b);
}

// Exactly monotone bucket map: fp add, mul by +const, float->int trunc are all
// monotone nondecreasing, so v1 <= v2 => bucket(v1) <= bucket(v2), and
// b1 < b2 => v1 < v2 (strict). Equal values map to equal buckets.
__device__ __forceinline__ int bucket_of(float v) {
    float f = (v + 6.0f) * ((float)NQ / 12.0f);
    f = fminf(fmaxf(f, 0.0f), (float)(NQ - 1));
    return (int)f;
}

// ---------------------------------------------------------------------------
// Kernel 1: per-column COUNTING sort of packed (value,index) u64 keys,
// with FUSED record emission (records built from smem-resident sorted keys —
// no separate record kernel, no global re-reads).
// grid = ND blocks, 512 threads x 2 elements.
// ---------------------------------------------------------------------------
__global__ void __launch_bounds__(512) sort_columns_kernel(const float* __restrict__ cent) {
    __shared__ __align__(16) int s_hist[NQ];       // 8 KB
    __shared__ __align__(16) int s_pref[NQ + 4];   // 8 KB (exclusive prefix)
    __shared__ u64 s_tmp[NK];                      // 8 KB (arrival-order scatter)
    __shared__ u64 s_keys[NK];                     // 8 KB (final sorted)
    __shared__ int s_wsum[16];

    const int d = blockIdx.x;
    const int i = threadIdx.x;
    const int lane = i & 31, w = i >> 5;

    if (d == 0 && i == 0) { g_accum = 0ULL; g_done = 0u; }  // per-launch reset

    const float v0 = cent[i * ND + d];
    const float v1 = cent[(i + 512) * ND + d];
    const u64 k0e = ((u64)enc_f32(v0) << 32) | (u32)i;
    const u64 k1e = ((u64)enc_f32(v1) << 32) | (u32)(i + 512);
    const int b0 = bucket_of(v0), b1 = bucket_of(v1);

    ((int4*)s_hist)[i] = make_int4(0, 0, 0, 0);   // NQ ints = 512 int4
    __syncthreads();
    const int r0 = atomicAdd(&s_hist[b0], 1);
    const int r1 = atomicAdd(&s_hist[b1], 1);
    __syncthreads();

    // prefix sum over 2048 bins (4 per thread)
    const int4 c = ((const int4*)s_hist)[i];
    const int s = c.x + c.y + c.z + c.w;
    int incl = s;
#pragma unroll
    for (int off = 1; off < 32; off <<= 1) {
        int t = __shfl_up_sync(0xffffffffu, incl, off);
        if (lane >= off) incl += t;
    }
    if (lane == 31) s_wsum[w] = incl;
    __syncthreads();
    if (w == 0) {
        int ws = (lane < 16) ? s_wsum[lane] : 0;
#pragma unroll
        for (int off = 1; off < 16; off <<= 1) {
            int t = __shfl_up_sync(0xffffffffu, ws, off);
            if (lane >= off) ws += t;
        }
        if (lane < 16) s_wsum[lane] = ws;
    }
    __syncthreads();
    {
        int p0 = (w > 0 ? s_wsum[w - 1] : 0) + (incl - s);
        ((int4*)s_pref)[i] = make_int4(p0, p0 + c.x, p0 + c.x + c.y, p0 + c.x + c.y + c.z);
    }
    if (i == 0) s_pref[NQ] = NK;
    __syncthreads();

    // scatter in arrival order
    const int st0 = s_pref[b0], st1 = s_pref[b1];
    s_tmp[st0 + r0] = k0e;
    s_tmp[st1 + r1] = k1e;
    __syncthreads();

    // parallel rank placement on unique full keys (deterministic)
    {
        const int cnt0 = s_hist[b0];
        int rank = 0;
        for (int j = 0; j < cnt0; j++) rank += (s_tmp[st0 + j] < k0e);
        s_keys[st0 + rank] = k0e;
        const int cnt1 = s_hist[b1];
        rank = 0;
        for (int j = 0; j < cnt1; j++) rank += (s_tmp[st1 + j] < k1e);
        s_keys[st1 + rank] = k1e;
    }
    __syncthreads();

    // sorted keys + lutpair (coalesced)
    g_skey[d * NK + i]       = s_keys[i];
    g_skey[d * NK + i + 512] = s_keys[i + 512];
#pragma unroll
    for (int t = 0; t < 4; t++) {
        const int q = i + t * 512;
        g_lutpair[d * NQ + q] = (u32)s_pref[q] | ((u32)s_pref[q + 1] << 16);
    }

    // fused record emission: 4 records per thread from smem-resident data
#pragma unroll
    for (int t = 0; t < 4; t++) {
        const int q = i + t * 512;
        const int st = s_pref[q], en = s_pref[q + 1];
        const u64 kl = s_keys[max(st - 1, 0)];
        const u64 k0 = s_keys[min(st, NK - 1)];
        const u64 k1 = s_keys[min(st + 1, NK - 1)];
        const u32 cc = (u32)min(en - st, 3);
        g_rec[d * NQ + q] = make_uint4(
            (u32)(kl >> 32), (u32)(k0 >> 32), (u32)(k1 >> 32),
            ((u32)kl & 1023u) | (((u32)k0 & 1023u) << 10) |
            (((u32)k1 & 1023u) << 20) | (cc << 30));
    }

    if (i == 0) {
        // min: first sorted key already has smallest index among min-ties
        g_vmin[d] = dec_f32((u32)(s_keys[0] >> 32));
        g_imin[d] = (int)(s_keys[0] & 1023u);
        // max: first occurrence (smallest idx) = start of the max-value run
        u32 umax = (u32)(s_keys[NK - 1] >> 32);
        int j = NK - 1;
        while (j > 0 && (u32)(s_keys[j - 1] >> 32) == umax) j--;
        g_vmax[d] = dec_f32(umax);
        g_imax[d] = (int)(s_keys[j] & 1023u);
    }
}

// ---------------------------------------------------------------------------
// Nearest-centroid resolve: one 16B record load resolves most queries
// (cnt<=1 or target<=k1); fallback loads lutpair + scans sorted keys.
// ---------------------------------------------------------------------------
__device__ __forceinline__ int resolve_near(const float xv, const int d) {
    const u32 te = enc_f32(xv);
    const int q = bucket_of(xv);
    const uint4 r = __ldg(&g_rec[d * NQ + q]);
    const u32 cc = r.w >> 30;

    u32 el, er, il, ir;
    if (cc == 0u || te <= r.y) {              // lower_bound = start
        el = r.x; il = r.w & 1023u;
        er = r.y; ir = (r.w >> 10) & 1023u;
    } else if (cc == 1u || te <= r.z) {       // lower_bound = start+1
        el = r.y; il = (r.w >> 10) & 1023u;
        er = r.z; ir = (r.w >> 20) & 1023u;
    } else {                                  // cnt>=2 and target beyond k1
        const u32 pr = __ldg(&g_lutpair[d * NQ + q]);
        const int st = (int)(pr & 0xffffu), en = (int)(pr >> 16);
        const int base = d * NK;
        const u64 target = ((u64)te) << 32;
        u64 prev = ((u64)r.z << 32) | ((r.w >> 20) & 1023u);
        u64 right = prev;
        bool found = false;
        for (int j = st + 2; j < en; j++) {
            u64 cur = __ldg(&g_skey[base + j]);
            if (cur >= target) { right = cur; found = true; break; }
            prev = cur;
        }
        if (!found) right = (en < NK) ? __ldg(&g_skey[base + en]) : prev;
        el = (u32)(prev >> 32);  il = (u32)prev & 1023u;
        er = (u32)(right >> 32); ir = (u32)right & 1023u;
    }

    const float vl = dec_f32(el), vr = dec_f32(er);
    float sl = xv - vl; sl *= sl;     // compare squares, like reference
    float sr = xv - vr; sr *= sr;
    return (sl < sr) ? (int)il : (sr < sl) ? (int)ir : min((int)il, (int)ir);
}

// ---------------------------------------------------------------------------
// Kernel 2: one block per TWO rows, ND threads (thread = dim d, both rows).
// - ONE byte-packed histogram (bytes: near0,near1,far0,far1; counts<=128)
// - task-parallel reductions: stage values to smem once, each WARP reduces a
//   whole 128-value array (instead of all threads walking all arrays)
// ---------------------------------------------------------------------------
__global__ void __launch_bounds__(ND) row_kernel(const float* __restrict__ x,
                                                 const float* __restrict__ cent,
                                                 float* __restrict__ out) {
    __shared__ u32 hist[NK];          // 4 KB
    __shared__ u32 s_stage[6 * ND];   // 3 KB, reused (keys then sums)
    __shared__ u32 s_resk[4];
    __shared__ float s_resf[6];

    const int b0 = blockIdx.x * 2;
    const int d = threadIdx.x;
    const int warp = d >> 5, lane = d & 31;

    {
        uint4 z = make_uint4(0, 0, 0, 0);
        ((uint4*)hist)[d] = z; ((uint4*)hist)[d + 128] = z;
    }

    const float xv0 = x[b0 * ND + d];
    const float xv1 = x[(b0 + 1) * ND + d];

    const int n0 = resolve_near(xv0, d);
    const int n1 = resolve_near(xv1, d);

    // farthest: one of the column extremes
    const float vmin = g_vmin[d], vmax = g_vmax[d];
    const int   imin = g_imin[d], imax = g_imax[d];
    int f0, f1;
    {
        float sm = xv0 - vmin; sm *= sm;
        float sM = xv0 - vmax; sM *= sM;
        f0 = (sm > sM) ? imin : (sM > sm) ? imax : min(imin, imax);
        sm = xv1 - vmin; sm *= sm;
        sM = xv1 - vmax; sM *= sM;
        f1 = (sm > sM) ? imin : (sM > sm) ? imax : min(imin, imax);
    }

    __syncthreads();  // hist zeroing complete
    // byte-lane atomics; counts <= 128 < 256 so no cross-byte carry
    u32 cn0 = ( atomicAdd(&hist[n0], 1u)        & 0xffu) + 1u;
    u32 cn1 = ((atomicAdd(&hist[n1], 1u << 8 )  >>  8) & 0xffu) + 1u;
    u32 cf0 = ((atomicAdd(&hist[f0], 1u << 16)  >> 16) & 0xffu) + 1u;
    u32 cf1 = ((atomicAdd(&hist[f1], 1u << 24)  >> 24)        ) + 1u;

    // mode keys: (count, smaller-index wins ties). Last incrementer of a bin
    // sees its final count, so max over all thread keys = the mode.
    s_stage[0 * ND + d] = (cn0 << 10) | (1023u - (u32)n0);
    s_stage[1 * ND + d] = (cn1 << 10) | (1023u - (u32)n1);
    s_stage[2 * ND + d] = (cf0 << 10) | (1023u - (u32)f0);
    s_stage[3 * ND + d] = (cf1 << 10) | (1023u - (u32)f1);
    __syncthreads();

    // each warp max-reduces one key array
    {
        const u32* a = &s_stage[warp * ND];
        u32 m = max(max(a[lane], a[lane + 32]), max(a[lane + 64], a[lane + 96]));
#pragma unroll
        for (int s = 16; s > 0; s >>= 1)
            m = max(m, __shfl_xor_sync(0xffffffffu, m, s));
        if (lane == 0) s_resk[warp] = m;
    }
    __syncthreads();

    const int mp0 = 1023 - (int)(s_resk[0] & 1023u);
    const int mp1 = 1023 - (int)(s_resk[1] & 1023u);
    const int mn0 = 1023 - (int)(s_resk[2] & 1023u);
    const int mn1 = 1023 - (int)(s_resk[3] & 1023u);

    // triplet terms (swap=True), eps added per element
    {
        const float pv0 = __ldg(&cent[mp0 * ND + d]);
        const float nv0 = __ldg(&cent[mn0 * ND + d]);
        const float pv1 = __ldg(&cent[mp1 * ND + d]);
        const float nv1 = __ldg(&cent[mn1 * ND + d]);
        float a0 = xv0 - pv0 + EPSV, b0f = xv0 - nv0 + EPSV, c0 = pv0 - nv0 + EPSV;
        float a1 = xv1 - pv1 + EPSV, b1f = xv1 - nv1 + EPSV, c1 = pv1 - nv1 + EPSV;
        s_stage[0 * ND + d] = __float_as_uint(a0 * a0);
        s_stage[1 * ND + d] = __float_as_uint(b0f * b0f);
        s_stage[2 * ND + d] = __float_as_uint(c0 * c0);
        s_stage[3 * ND + d] = __float_as_uint(a1 * a1);
        s_stage[4 * ND + d] = __float_as_uint(b1f * b1f);
        s_stage[5 * ND + d] = __float_as_uint(c1 * c1);
    }
    __syncthreads();

    // 6 sum tasks over 4 warps (warp w: task w, and w+4 if w<2)
#pragma unroll
    for (int rep = 0; rep < 2; rep++) {
        const int t = warp + rep * 4;
        if (t < 6) {
            const u32* a = &s_stage[t * ND];
            float v = (__uint_as_float(a[lane]) + __uint_as_float(a[lane + 32]))
                    + (__uint_as_float(a[lane + 64]) + __uint_as_float(a[lane + 96]));
#pragma unroll
            for (int s = 16; s > 0; s >>= 1)
                v += __shfl_xor_sync(0xffffffffu, v, s);
            if (lane == 0) s_resf[t] = v;
        }
    }
    __syncthreads();

    if (d == 0) {
        float dp0 = sqrtf(s_resf[0]);
        float dn0 = fminf(sqrtf(s_resf[1]), sqrtf(s_resf[2]));
        float loss0 = fmaxf(dp0 - dn0 + 1.0f, 0.0f);
        float dp1 = sqrtf(s_resf[3]);
        float dn1 = fminf(sqrtf(s_resf[4]), sqrtf(s_resf[5]));
        float loss1 = fmaxf(dp1 - dn1 + 1.0f, 0.0f);

        // deterministic fixed-point accumulation (integer adds are associative)
        u64 fx = (u64)__double2ll_rn((double)loss0 * SCALE)
               + (u64)__double2ll_rn((double)loss1 * SCALE);
        atomicAdd(&g_accum, fx);
        __threadfence();
        if (atomicAdd(&g_done, 1u) == gridDim.x - 1) {
            u64 acc = atomicAdd(&g_accum, 0ULL);
            out[0] = (float)((double)acc * (1.0 / (4096.0 * SCALE)));
        }
    }
}

extern "C" void kernel_launch(void* const* d_in, const int* in_sizes, int n_in,
                              void* d_out, int out_size) {
    const float* input_features = (const float*)d_in[0];  // [4096, 128]
    const float* centroids      = (const float*)d_in[1];  // [1024, 128]
    float* out = (float*)d_out;

    sort_columns_kernel<<<ND, 512>>>(centroids);
    row_kernel<<<NB / 2, ND>>>(input_features, centroids, out);
}

// round 10
// speedup vs baseline: 1.3726x; 1.0381x over previous
#include <cuda_runtime.h>
#include <math.h>

#define NB 4096
#define NK 1024
#define ND 128
#define NQ 2048
#define RPB 8                 // rows per block (1 warp per row)
#define EPSV 1e-6f
#define SCALE 4294967296.0    // 2^32 fixed-point for deterministic accumulation
#define CNT_SHIFT 50          // block-counter bits in the global accumulator

typedef unsigned long long u64;
typedef unsigned int u32;

// Scratch (device globals — no allocation allowed in kernel_launch)
__device__ u64    g_skey[ND * NK];     // sorted packed keys, layout [d][i]
__device__ u32    g_lutpair[ND * NQ];  // per-bucket start|end<<16 (fallback only)
__device__ uint4  g_rec[ND * NQ];      // 16B: kl_enc,k0_enc,k1_enc, idx+cnt pack
__device__ float4 g_vmin4[ND / 4], g_vmax4[ND / 4];
__device__ int4   g_imin4[ND / 4], g_imax4[ND / 4];
__device__ u64    g_accum;             // fixed-point sum + block counter (bits 50+)

// float -> order-preserving u32 (ascending)
__device__ __forceinline__ u32 enc_f32(float v) {
    u32 b = __float_as_uint(v);
    return (b & 0x80000000u) ? ~b : (b | 0x80000000u);
}
__device__ __forceinline__ float dec_f32(u32 u) {
    u32 b = (u & 0x80000000u) ? (u ^ 0x80000000u) : ~u;
    return __uint_as_float(b);
}

// Exactly monotone bucket map: fp add, mul by +const, float->int trunc are all
// monotone nondecreasing, so v1 <= v2 => bucket(v1) <= bucket(v2), and
// b1 < b2 => v1 < v2 (strict). Equal values map to equal buckets.
__device__ __forceinline__ int bucket_of(float v) {
    float f = (v + 6.0f) * ((float)NQ / 12.0f);
    f = fminf(fmaxf(f, 0.0f), (float)(NQ - 1));
    return (int)f;
}

// ---------------------------------------------------------------------------
// Kernel 1: per-column COUNTING sort of packed (value,index) u64 keys.
// 1024 threads, ONE element per thread -> every serial phase halves vs 512x2.
// Fused lutpair + record emission from smem-resident sorted keys.
// ---------------------------------------------------------------------------
__global__ void __launch_bounds__(1024) sort_columns_kernel(const float* __restrict__ cent) {
    __shared__ __align__(16) int s_hist[NQ];       // 8 KB
    __shared__ __align__(16) int s_pref[NQ + 4];   // 8 KB (exclusive prefix)
    __shared__ u64 s_tmp[NK];                      // 8 KB (arrival-order scatter)
    __shared__ u64 s_keys[NK];                     // 8 KB (final sorted)
    __shared__ int s_wsum[32];

    const int d = blockIdx.x;
    const int i = threadIdx.x;
    const int lane = i & 31, w = i >> 5;

    if (d == 0 && i == 0) g_accum = 0ULL;   // per-launch accumulator reset

    const float v = cent[i * ND + d];
    const u64 key = ((u64)enc_f32(v) << 32) | (u32)i;
    const int bkt = bucket_of(v);

    ((int2*)s_hist)[i] = make_int2(0, 0);   // NQ ints = 1024 int2
    __syncthreads();
    const int r = atomicAdd(&s_hist[bkt], 1);
    __syncthreads();

    // prefix sum over 2048 bins (2 per thread)
    const int2 c = ((const int2*)s_hist)[i];
    const int s = c.x + c.y;
    int incl = s;
#pragma unroll
    for (int off = 1; off < 32; off <<= 1) {
        int t = __shfl_up_sync(0xffffffffu, incl, off);
        if (lane >= off) incl += t;
    }
    if (lane == 31) s_wsum[w] = incl;
    __syncthreads();
    if (w == 0) {
        int ws = s_wsum[lane];
#pragma unroll
        for (int off = 1; off < 32; off <<= 1) {
            int t = __shfl_up_sync(0xffffffffu, ws, off);
            if (lane >= off) ws += t;
        }
        s_wsum[lane] = ws;
    }
    __syncthreads();
    {
        int p0 = (w > 0 ? s_wsum[w - 1] : 0) + (incl - s);
        ((int2*)s_pref)[i] = make_int2(p0, p0 + c.x);
    }
    if (i == 0) s_pref[NQ] = NK;
    __syncthreads();

    // scatter in arrival order
    const int st = s_pref[bkt];
    s_tmp[st + r] = key;
    __syncthreads();

    // parallel rank placement on unique full keys (deterministic)
    {
        const int cnt = s_hist[bkt];
        int rank = 0;
        for (int j = 0; j < cnt; j++) rank += (s_tmp[st + j] < key);
        s_keys[st + rank] = key;
    }
    __syncthreads();

    g_skey[d * NK + i] = s_keys[i];   // coalesced

    // lutpair + record: 2 buckets per thread, from smem-resident data
#pragma unroll
    for (int t = 0; t < 2; t++) {
        const int q = i + t * 1024;
        const int qs = s_pref[q], qe = s_pref[q + 1];
        g_lutpair[d * NQ + q] = (u32)qs | ((u32)qe << 16);
        const u64 kl = s_keys[max(qs - 1, 0)];
        const u64 k0 = s_keys[min(qs, NK - 1)];
        const u64 k1 = s_keys[min(qs + 1, NK - 1)];
        const u32 cc = (u32)min(qe - qs, 3);
        g_rec[d * NQ + q] = make_uint4(
            (u32)(kl >> 32), (u32)(k0 >> 32), (u32)(k1 >> 32),
            ((u32)kl & 1023u) | (((u32)k0 & 1023u) << 10) |
            (((u32)k1 & 1023u) << 20) | (cc << 30));
    }

    if (i == 0) {
        // min: first sorted key already has smallest index among min-ties
        ((float*)g_vmin4)[d] = dec_f32((u32)(s_keys[0] >> 32));
        ((int*)g_imin4)[d]   = (int)(s_keys[0] & 1023u);
        // max: first occurrence (smallest idx) = start of the max-value run
        u32 umax = (u32)(s_keys[NK - 1] >> 32);
        int j = NK - 1;
        while (j > 0 && (u32)(s_keys[j - 1] >> 32) == umax) j--;
        ((float*)g_vmax4)[d] = dec_f32(umax);
        ((int*)g_imax4)[d]   = (int)(s_keys[j] & 1023u);
    }
}

// ---------------------------------------------------------------------------
// Nearest-centroid resolve: one 16B record load resolves most queries
// (cnt<=1 or target<=k1); fallback loads lutpair + scans sorted keys.
// ---------------------------------------------------------------------------
__device__ __forceinline__ int resolve_near(const float xv, const int d) {
    const u32 te = enc_f32(xv);
    const int q = bucket_of(xv);
    const uint4 r = __ldg(&g_rec[d * NQ + q]);
    const u32 cc = r.w >> 30;

    u32 el, er, il, ir;
    if (cc == 0u || te <= r.y) {              // lower_bound = start
        el = r.x; il = r.w & 1023u;
        er = r.y; ir = (r.w >> 10) & 1023u;
    } else if (cc == 1u || te <= r.z) {       // lower_bound = start+1
        el = r.y; il = (r.w >> 10) & 1023u;
        er = r.z; ir = (r.w >> 20) & 1023u;
    } else {                                  // cnt>=2 and target beyond k1
        const u32 pr = __ldg(&g_lutpair[d * NQ + q]);
        const int st = (int)(pr & 0xffffu), en = (int)(pr >> 16);
        const int base = d * NK;
        const u64 target = ((u64)te) << 32;
        u64 prev = ((u64)r.z << 32) | ((r.w >> 20) & 1023u);
        u64 right = prev;
        bool found = false;
        for (int j = st + 2; j < en; j++) {
            u64 cur = __ldg(&g_skey[base + j]);
            if (cur >= target) { right = cur; found = true; break; }
            prev = cur;
        }
        if (!found) right = (en < NK) ? __ldg(&g_skey[base + en]) : prev;
        el = (u32)(prev >> 32);  il = (u32)prev & 1023u;
        er = (u32)(right >> 32); ir = (u32)right & 1023u;
    }

    const float vl = dec_f32(el), vr = dec_f32(er);
    float sl = xv - vl; sl *= sl;     // compare squares, like reference
    float sr = xv - vr; sr *= sr;
    return (sl < sr) ? (int)il : (sr < sl) ? (int)ir : min((int)il, (int)ir);
}

// ---------------------------------------------------------------------------
// Kernel 2: ONE WARP PER ROW, 8 rows per 256-thread block.
// Thread = 4 consecutive dims (float4). All reductions are warp-local shfl.
// Histograms: 4 warps share one u32 array via byte lanes (counts <= 128, no
// carry); reading back only your own byte needs no cross-warp sync.
// Block barriers: 1 (zeroing) + 1 (block accumulator).
// ---------------------------------------------------------------------------
__global__ void __launch_bounds__(2 * ND) row_kernel(const float* __restrict__ x,
                                                     const float* __restrict__ cent,
                                                     float* __restrict__ out) {
    __shared__ u32 histN[2][NK];   // 8 KB (near counts, byte-packed 4 rows)
    __shared__ u32 histF[2][NK];   // 8 KB (far counts)
    __shared__ u64 s_acc;

    const int tid = threadIdx.x;
    const int warp = tid >> 5, lane = tid & 31;
    const int grp = warp >> 2;           // which hist array
    const int sh = (warp & 3) * 8;       // byte lane within it
    const int row = blockIdx.x * RPB + warp;

    // zero both hist arrays (1024 uint4 total / 256 threads = 4 each) + s_acc
    {
        uint4 z = make_uint4(0, 0, 0, 0);
        ((uint4*)histN)[tid] = z; ((uint4*)histN)[tid + 256] = z;
        ((uint4*)histF)[tid] = z; ((uint4*)histF)[tid + 256] = z;
    }
    if (tid == 0) s_acc = 0ULL;
    __syncthreads();

    // this thread's 4 dims: d = lane*4 + j
    const float4 xq = __ldg((const float4*)x + row * 32 + lane);
    float xv[4] = { xq.x, xq.y, xq.z, xq.w };

    int n_idx[4];
#pragma unroll
    for (int j = 0; j < 4; j++) n_idx[j] = resolve_near(xv[j], lane * 4 + j);

    // farthest: one of the column extremes
    const float4 vmn = g_vmin4[lane];
    const float4 vmx = g_vmax4[lane];
    const int4   imn = g_imin4[lane];
    const int4   imx = g_imax4[lane];
    const float vmin[4] = { vmn.x, vmn.y, vmn.z, vmn.w };
    const float vmax[4] = { vmx.x, vmx.y, vmx.z, vmx.w };
    const int   imin_[4] = { imn.x, imn.y, imn.z, imn.w };
    const int   imax_[4] = { imx.x, imx.y, imx.z, imx.w };
    int f_idx[4];
#pragma unroll
    for (int j = 0; j < 4; j++) {
        float sm = xv[j] - vmin[j]; sm *= sm;
        float sM = xv[j] - vmax[j]; sM *= sM;
        f_idx[j] = (sm > sM) ? imin_[j]
                 : (sM > sm) ? imax_[j]
                 : min(imin_[j], imax_[j]);
    }

    // histogram + running-max mode key. Last incrementer of a byte lane sees
    // its final count; other bytes in the word don't affect ours.
    u32 keyN = 0, keyF = 0;
#pragma unroll
    for (int j = 0; j < 4; j++) {
        u32 cn = ((atomicAdd(&histN[grp][n_idx[j]], 1u << sh) >> sh) & 0xffu) + 1u;
        u32 cf = ((atomicAdd(&histF[grp][f_idx[j]], 1u << sh) >> sh) & 0xffu) + 1u;
        keyN = max(keyN, (cn << 10) | (1023u - (u32)n_idx[j]));
        keyF = max(keyF, (cf << 10) | (1023u - (u32)f_idx[j]));
    }
#pragma unroll
    for (int s = 16; s > 0; s >>= 1) {
        keyN = max(keyN, __shfl_xor_sync(0xffffffffu, keyN, s));
        keyF = max(keyF, __shfl_xor_sync(0xffffffffu, keyF, s));
    }
    const int mp = 1023 - (int)(keyN & 1023u);
    const int mn = 1023 - (int)(keyF & 1023u);

    // triplet margin loss (swap=True), eps added per element
    const float4 pq = __ldg((const float4*)cent + mp * 32 + lane);
    const float4 nq = __ldg((const float4*)cent + mn * 32 + lane);
    const float pv[4] = { pq.x, pq.y, pq.z, pq.w };
    const float nv[4] = { nq.x, nq.y, nq.z, nq.w };
    float t0 = 0.0f, t1 = 0.0f, t2 = 0.0f;
#pragma unroll
    for (int j = 0; j < 4; j++) {
        float a = xv[j] - pv[j] + EPSV;
        float b = xv[j] - nv[j] + EPSV;
        float c = pv[j] - nv[j] + EPSV;
        t0 = fmaf(a, a, t0);
        t1 = fmaf(b, b, t1);
        t2 = fmaf(c, c, t2);
    }
#pragma unroll
    for (int s = 16; s > 0; s >>= 1) {
        t0 += __shfl_xor_sync(0xffffffffu, t0, s);
        t1 += __shfl_xor_sync(0xffffffffu, t1, s);
        t2 += __shfl_xor_sync(0xffffffffu, t2, s);
    }

    if (lane == 0) {
        float dp = sqrtf(t0);
        float dn = fminf(sqrtf(t1), sqrtf(t2));
        float loss = fmaxf(dp - dn + 1.0f, 0.0f);
        // deterministic fixed-point accumulation (integer adds associative)
        u64 fx = (u64)__double2ll_rn((double)loss * SCALE);
        atomicAdd(&s_acc, fx);
    }
    __syncthreads();

    if (tid == 0) {
        // counter embedded in the same atomic word: when the returned counter
        // equals grid-1, all other blocks' sums are already in the low bits.
        u64 mine = s_acc;
        u64 ret = atomicAdd(&g_accum, mine + (1ULL << CNT_SHIFT));
        if ((ret >> CNT_SHIFT) == (u64)(gridDim.x - 1)) {
            u64 total = ((ret & ((1ULL << CNT_SHIFT) - 1)) + mine);
            out[0] = (float)((double)total * (1.0 / (4096.0 * SCALE)));
        }
    }
}

extern "C" void kernel_launch(void* const* d_in, const int* in_sizes, int n_in,
                              void* d_out, int out_size) {
    const float* input_features = (const float*)d_in[0];  // [4096, 128]
    const float* centroids      = (const float*)d_in[1];  // [1024, 128]
    float* out = (float*)d_out;

    sort_columns_kernel<<<ND, 1024>>>(centroids);
    row_kernel<<<NB / RPB, 2 * ND>>>(input_features, centroids, out);
}

// round 11
// speedup vs baseline: 1.5000x; 1.0928x over previous
#include <cuda_runtime.h>
#include <math.h>

#define NB 4096
#define NK 1024
#define ND 128
#define NQ 2048
#define EPSV 1e-6f
#define SCALE 4294967296.0    // 2^32 fixed-point for deterministic accumulation
#define CNT_SHIFT 50          // row-counter bits in the global accumulator

typedef unsigned long long u64;
typedef unsigned int u32;

// Scratch (device globals — no allocation allowed in kernel_launch)
__device__ u64    g_skey[ND * NK];     // sorted packed keys, layout [d][i]
__device__ u32    g_lutpair[ND * NQ];  // per-bucket start|end<<16 (fallback only)
__device__ uint4  g_rec[ND * NQ];      // 16B: kl_enc,k0_enc,k1_enc, idx+cnt pack
__device__ float2 g_vmin2[ND / 2], g_vmax2[ND / 2];
__device__ int2   g_imin2[ND / 2], g_imax2[ND / 2];
__device__ u64    g_accum;             // fixed-point sum + row counter (bits 50+)

// float -> order-preserving u32 (ascending)
__device__ __forceinline__ u32 enc_f32(float v) {
    u32 b = __float_as_uint(v);
    return (b & 0x80000000u) ? ~b : (b | 0x80000000u);
}
__device__ __forceinline__ float dec_f32(u32 u) {
    u32 b = (u & 0x80000000u) ? (u ^ 0x80000000u) : ~u;
    return __uint_as_float(b);
}

// Exactly monotone bucket map: fp add, mul by +const, float->int trunc are all
// monotone nondecreasing, so v1 <= v2 => bucket(v1) <= bucket(v2), and
// b1 < b2 => v1 < v2 (strict). Equal values map to equal buckets.
__device__ __forceinline__ int bucket_of(float v) {
    float f = (v + 6.0f) * ((float)NQ / 12.0f);
    f = fminf(fmaxf(f, 0.0f), (float)(NQ - 1));
    return (int)f;
}

// ---------------------------------------------------------------------------
// Kernel 1: per-column COUNTING sort of packed (value,index) u64 keys.
// 1024 threads, one element per thread. Fused lutpair + record emission.
// ---------------------------------------------------------------------------
__global__ void __launch_bounds__(1024) sort_columns_kernel(const float* __restrict__ cent) {
    __shared__ __align__(16) int s_hist[NQ];       // 8 KB
    __shared__ __align__(16) int s_pref[NQ + 4];   // 8 KB (exclusive prefix)
    __shared__ u64 s_tmp[NK];                      // 8 KB (arrival-order scatter)
    __shared__ u64 s_keys[NK];                     // 8 KB (final sorted)
    __shared__ int s_wsum[32];

    const int d = blockIdx.x;
    const int i = threadIdx.x;
    const int lane = i & 31, w = i >> 5;

    if (d == 0 && i == 0) g_accum = 0ULL;   // per-launch accumulator reset

    const float v = cent[i * ND + d];
    const u64 key = ((u64)enc_f32(v) << 32) | (u32)i;
    const int bkt = bucket_of(v);

    ((int2*)s_hist)[i] = make_int2(0, 0);   // NQ ints = 1024 int2
    __syncthreads();
    const int r = atomicAdd(&s_hist[bkt], 1);
    __syncthreads();

    // prefix sum over 2048 bins (2 per thread)
    const int2 c = ((const int2*)s_hist)[i];
    const int s = c.x + c.y;
    int incl = s;
#pragma unroll
    for (int off = 1; off < 32; off <<= 1) {
        int t = __shfl_up_sync(0xffffffffu, incl, off);
        if (lane >= off) incl += t;
    }
    if (lane == 31) s_wsum[w] = incl;
    __syncthreads();
    if (w == 0) {
        int ws = s_wsum[lane];
#pragma unroll
        for (int off = 1; off < 32; off <<= 1) {
            int t = __shfl_up_sync(0xffffffffu, ws, off);
            if (lane >= off) ws += t;
        }
        s_wsum[lane] = ws;
    }
    __syncthreads();
    {
        int p0 = (w > 0 ? s_wsum[w - 1] : 0) + (incl - s);
        ((int2*)s_pref)[i] = make_int2(p0, p0 + c.x);
    }
    if (i == 0) s_pref[NQ] = NK;
    __syncthreads();

    // scatter in arrival order
    const int st = s_pref[bkt];
    s_tmp[st + r] = key;
    __syncthreads();

    // parallel rank placement on unique full keys (deterministic)
    {
        const int cnt = s_hist[bkt];
        int rank = 0;
        for (int j = 0; j < cnt; j++) rank += (s_tmp[st + j] < key);
        s_keys[st + rank] = key;
    }
    __syncthreads();

    g_skey[d * NK + i] = s_keys[i];   // coalesced

    // lutpair + record: 2 buckets per thread, from smem-resident data
#pragma unroll
    for (int t = 0; t < 2; t++) {
        const int q = i + t * 1024;
        const int qs = s_pref[q], qe = s_pref[q + 1];
        g_lutpair[d * NQ + q] = (u32)qs | ((u32)qe << 16);
        const u64 kl = s_keys[max(qs - 1, 0)];
        const u64 k0 = s_keys[min(qs, NK - 1)];
        const u64 k1 = s_keys[min(qs + 1, NK - 1)];
        const u32 cc = (u32)min(qe - qs, 3);
        g_rec[d * NQ + q] = make_uint4(
            (u32)(kl >> 32), (u32)(k0 >> 32), (u32)(k1 >> 32),
            ((u32)kl & 1023u) | (((u32)k0 & 1023u) << 10) |
            (((u32)k1 & 1023u) << 20) | (cc << 30));
    }

    if (i == 0) {
        // min: first sorted key already has smallest index among min-ties
        ((float*)g_vmin2)[d] = dec_f32((u32)(s_keys[0] >> 32));
        ((int*)g_imin2)[d]   = (int)(s_keys[0] & 1023u);
        // max: first occurrence (smallest idx) = start of the max-value run
        u32 umax = (u32)(s_keys[NK - 1] >> 32);
        int j = NK - 1;
        while (j > 0 && (u32)(s_keys[j - 1] >> 32) == umax) j--;
        ((float*)g_vmax2)[d] = dec_f32(umax);
        ((int*)g_imax2)[d]   = (int)(s_keys[j] & 1023u);
    }
}

// ---------------------------------------------------------------------------
// Nearest-centroid resolve: one 16B record load resolves most queries
// (cnt<=1 or target<=k1); fallback loads lutpair + scans sorted keys.
// ---------------------------------------------------------------------------
__device__ __forceinline__ int resolve_near(const float xv, const int d) {
    const u32 te = enc_f32(xv);
    const int q = bucket_of(xv);
    const uint4 r = __ldg(&g_rec[d * NQ + q]);
    const u32 cc = r.w >> 30;

    u32 el, er, il, ir;
    if (cc == 0u || te <= r.y) {              // lower_bound = start
        el = r.x; il = r.w & 1023u;
        er = r.y; ir = (r.w >> 10) & 1023u;
    } else if (cc == 1u || te <= r.z) {       // lower_bound = start+1
        el = r.y; il = (r.w >> 10) & 1023u;
        er = r.z; ir = (r.w >> 20) & 1023u;
    } else {                                  // cnt>=2 and target beyond k1
        const u32 pr = __ldg(&g_lutpair[d * NQ + q]);
        const int st = (int)(pr & 0xffffu), en = (int)(pr >> 16);
        const int base = d * NK;
        const u64 target = ((u64)te) << 32;
        u64 prev = ((u64)r.z << 32) | ((r.w >> 20) & 1023u);
        u64 right = prev;
        bool found = false;
        for (int j = st + 2; j < en; j++) {
            u64 cur = __ldg(&g_skey[base + j]);
            if (cur >= target) { right = cur; found = true; break; }
            prev = cur;
        }
        if (!found) right = (en < NK) ? __ldg(&g_skey[base + en]) : prev;
        el = (u32)(prev >> 32);  il = (u32)prev & 1023u;
        er = (u32)(right >> 32); ir = (u32)right & 1023u;
    }

    const float vl = dec_f32(el), vr = dec_f32(er);
    float sl = xv - vl; sl *= sl;     // compare squares, like reference
    float sr = xv - vr; sr *= sr;
    return (sl < sr) ? (int)il : (sr < sl) ? (int)ir : min((int)il, (int)ir);
}

// ---------------------------------------------------------------------------
// Kernel 2: TWO WARPS PER ROW (half-row each, 2 dims/thread), 2 rows per
// 128-thread block -> 8192 warps chip-wide (~86% occupancy ceiling).
// One 4 KB histogram, byte lanes = {near r0, near r1, far r0, far r1}.
// Mode: running-max trick composes across the warp pair (the globally-last
// increment of a bin carries the final count and lands in one warp's max).
// ---------------------------------------------------------------------------
__global__ void __launch_bounds__(ND) row_kernel(const float* __restrict__ x,
                                                 const float* __restrict__ cent,
                                                 float* __restrict__ out) {
    __shared__ u32 hist[NK];          // 4 KB
    __shared__ u32 s_keys[4][2];      // per-warp partial mode keys (N, F)
    __shared__ float s_part[4][3];    // per-warp partial distance sums

    const int tid = threadIdx.x;
    const int warp = tid >> 5, lane = tid & 31;
    const int rowb = warp >> 1;          // row within block (0/1)
    const int half = warp & 1;           // which 64-dim half
    const int row = blockIdx.x * 2 + rowb;
    const int shN = rowb * 8;            // byte lane for near counts
    const int shF = 16 + rowb * 8;       // byte lane for far counts

    // zero hist: 256 uint4 / 128 threads = 2 each
    {
        uint4 z = make_uint4(0, 0, 0, 0);
        ((uint4*)hist)[tid] = z;
        ((uint4*)hist)[tid + 128] = z;
    }
    __syncthreads();

    // this thread's 2 dims: d0 = half*64 + lane*2
    const int dh = half * 32 + lane;                  // float2 index
    const int d0 = 2 * dh;
    const float2 xv = __ldg((const float2*)x + row * 64 + dh);

    const int n0 = resolve_near(xv.x, d0);
    const int n1 = resolve_near(xv.y, d0 + 1);

    // farthest: one of the column extremes
    const float2 vmn = g_vmin2[dh], vmx = g_vmax2[dh];
    const int2   imn = g_imin2[dh], imx = g_imax2[dh];
    int f0, f1;
    {
        float sm = xv.x - vmn.x; sm *= sm;
        float sM = xv.x - vmx.x; sM *= sM;
        f0 = (sm > sM) ? imn.x : (sM > sm) ? imx.x : min(imn.x, imx.x);
        sm = xv.y - vmn.y; sm *= sm;
        sM = xv.y - vmx.y; sM *= sM;
        f1 = (sm > sM) ? imn.y : (sM > sm) ? imx.y : min(imn.y, imx.y);
    }

    // histogram (byte lanes; counts <= 128, no carry) + running-max mode keys
    u32 keyN, keyF;
    {
        u32 cn0 = ((atomicAdd(&hist[n0], 1u << shN) >> shN) & 0xffu) + 1u;
        u32 cn1 = ((atomicAdd(&hist[n1], 1u << shN) >> shN) & 0xffu) + 1u;
        u32 cf0 = ((atomicAdd(&hist[f0], 1u << shF) >> shF) & 0xffu) + 1u;
        u32 cf1 = ((atomicAdd(&hist[f1], 1u << shF) >> shF) & 0xffu) + 1u;
        keyN = max((cn0 << 10) | (1023u - (u32)n0), (cn1 << 10) | (1023u - (u32)n1));
        keyF = max((cf0 << 10) | (1023u - (u32)f0), (cf1 << 10) | (1023u - (u32)f1));
    }
#pragma unroll
    for (int s = 16; s > 0; s >>= 1) {
        keyN = max(keyN, __shfl_xor_sync(0xffffffffu, keyN, s));
        keyF = max(keyF, __shfl_xor_sync(0xffffffffu, keyF, s));
    }
    if (lane == 0) { s_keys[warp][0] = keyN; s_keys[warp][1] = keyF; }
    __syncthreads();

    // combine the warp pair's partial keys -> row mode
    const int pw = warp ^ 1;
    const u32 kN = max(s_keys[warp][0], s_keys[pw][0]);
    const u32 kF = max(s_keys[warp][1], s_keys[pw][1]);
    const int mp = 1023 - (int)(kN & 1023u);
    const int mn = 1023 - (int)(kF & 1023u);

    // triplet terms (swap=True), eps added per element; partial over 64 dims
    const float2 pv = __ldg((const float2*)cent + mp * 64 + dh);
    const float2 nv = __ldg((const float2*)cent + mn * 64 + dh);
    float t0, t1, t2;
    {
        float a = xv.x - pv.x + EPSV;
        float b = xv.x - nv.x + EPSV;
        float c = pv.x - nv.x + EPSV;
        t0 = a * a; t1 = b * b; t2 = c * c;
        a = xv.y - pv.y + EPSV;
        b = xv.y - nv.y + EPSV;
        c = pv.y - nv.y + EPSV;
        t0 = fmaf(a, a, t0); t1 = fmaf(b, b, t1); t2 = fmaf(c, c, t2);
    }
#pragma unroll
    for (int s = 16; s > 0; s >>= 1) {
        t0 += __shfl_xor_sync(0xffffffffu, t0, s);
        t1 += __shfl_xor_sync(0xffffffffu, t1, s);
        t2 += __shfl_xor_sync(0xffffffffu, t2, s);
    }
    if (lane == 0) {
        s_part[warp][0] = t0; s_part[warp][1] = t1; s_part[warp][2] = t2;
    }
    __syncthreads();

    // one owner warp per row (half==0) finishes the loss
    if (half == 0 && lane == 0) {
        float r0 = s_part[warp][0] + s_part[warp + 1][0];
        float r1 = s_part[warp][1] + s_part[warp + 1][1];
        float r2 = s_part[warp][2] + s_part[warp + 1][2];
        float dp = sqrtf(r0);
        float dn = fminf(sqrtf(r1), sqrtf(r2));
        float loss = fmaxf(dp - dn + 1.0f, 0.0f);

        // deterministic fixed-point accumulation with embedded row counter:
        // when the returned counter == NB-1, all other rows' sums are in.
        u64 fx = (u64)__double2ll_rn((double)loss * SCALE);
        u64 ret = atomicAdd(&g_accum, fx + (1ULL << CNT_SHIFT));
        if ((ret >> CNT_SHIFT) == (u64)(NB - 1)) {
            u64 total = (ret & ((1ULL << CNT_SHIFT) - 1)) + fx;
            out[0] = (float)((double)total * (1.0 / (4096.0 * SCALE)));
        }
    }
}

extern "C" void kernel_launch(void* const* d_in, const int* in_sizes, int n_in,
                              void* d_out, int out_size) {
    const float* input_features = (const float*)d_in[0];  // [4096, 128]
    const float* centroids      = (const float*)d_in[1];  // [1024, 128]
    float* out = (float*)d_out;

    sort_columns_kernel<<<ND, 1024>>>(centroids);
    row_kernel<<<NB / 2, ND>>>(input_features, centroids, out);
}